// round 4
// baseline (speedup 1.0000x reference)
#include <cuda_runtime.h>
#include <math.h>

// ---------------------------------------------------------------------------
// DeepJ biaxial LSTM.
//   B=1024, N=48, TU=256, NU=128, IN_T=50 (padded to 64), IN_N=257.
// Key simplifications vs reference:
//   - time-axis LSTM layers run a SINGLE step with h=c=0 => Whh terms and
//     f-gates are dead; they are feed-forward gate-GEMMs.
//   - note-axis scan is sequential in n but independent per batch => one
//     persistent block owns 8 batches for all 48 steps (no grid sync).
//   - feats @ n_Wih0[:, :256].T precomputed as one big GEMM (g_xw).
// ---------------------------------------------------------------------------

#define BB 1024
#define NN 48
#define MM (BB * NN)   // 49152
#define K1 64          // IN_T=50 padded to 64

// scratch (device globals: allocation-free)
__device__ float g_rnnin[MM * K1];            // 12.6 MB
__device__ float g_w0p[1024 * K1];            // padded t_Wih0
__device__ float g_h1[MM * 256];              // 48 MB
__device__ float g_feats[MM * 256];           // 48 MB
__device__ float g_w2p[512 * 256];            // n_Wih0[:, :256] contiguous
__device__ float g_wc[512];                   // n_Wih0[:, 256] (cond column)
__device__ float g_xw[MM * 512];              // 96 MB

__device__ __forceinline__ float sigf(float x) { return 1.0f / (1.0f + expf(-x)); }

// ------------------------------ prep kernels ------------------------------

__global__ void build_rnnin(const float* __restrict__ note) {
    int idx = blockIdx.x * blockDim.x + threadIdx.x;
    if (idx >= MM * K1) return;
    int f = idx & 63;
    int m = idx >> 6;
    int b = m / NN, n = m % NN;
    float v = 0.0f;
    if (f == 0) {
        v = (float)n * (1.0f / (float)NN);
    } else if (f < 13) {
        v = ((f - 1) == (n % 12)) ? 1.0f : 0.0f;
    } else if (f < 38) {
        int p = n + (f - 13) - 12;
        v = (p >= 0 && p < NN) ? note[b * NN + p] : 0.0f;
    } else if (f < 50) {
        const float* nb = note + b * NN + (f - 38) * 4;
        v = nb[0] + nb[1] + nb[2] + nb[3];
    }
    g_rnnin[idx] = v;
}

__global__ void pad_w0(const float* __restrict__ w) {  // (1024, 50) -> (1024, 64)
    int idx = blockIdx.x * blockDim.x + threadIdx.x;
    if (idx >= 1024 * K1) return;
    int k = idx & 63, r = idx >> 6;
    g_w0p[idx] = (k < 50) ? w[r * 50 + k] : 0.0f;
}

__global__ void prep_w2(const float* __restrict__ w) {  // n_Wih0 (512, 257)
    int idx = blockIdx.x * blockDim.x + threadIdx.x;
    if (idx >= 512 * 256) return;
    int k = idx & 255, r = idx >> 8;
    g_w2p[idx] = w[r * 257 + k];
    if (k == 0) g_wc[r] = w[r * 257 + 256];
}

// ------------------------- feed-forward gate GEMM -------------------------
// Computes gates = X @ W.T (+bias) for an LSTM with zero initial state.
// ACT=true : skip dead f-gate, emit h[m, u] = sig(o)*tanh(sig(i)*tanh(g)).
// ACT=false: emit all 4 raw gate columns out[m, gate*U + u]  (bias unused).
// Tiling: 64 rows x 32 units per block, 256 threads, K tiles of 16, double
// buffered shared staging.

template <int U, bool ACT>
__global__ __launch_bounds__(256)
void lstm_gemm(const float* __restrict__ X, int ldx, int KTOT,
               const float* __restrict__ W,
               const float* __restrict__ bias,
               float* __restrict__ out) {
    constexpr int NG = ACT ? 3 : 4;
    constexpr int NC = NG * 32;

    __shared__ float sXT[2][16][64];   // [k][m]
    __shared__ float sWT[2][16][NC];   // [k][c], c = gs*32 + u_local

    const int t = threadIdx.x;
    const int tx = t & 15, ty = t >> 4;
    const int m0 = blockIdx.x * 64;
    const int u0 = blockIdx.y * 32;

    // X loader: 64 rows x 16 k = 256 float4, one per thread
    const int xm = t >> 2, xk = (t & 3) * 4;
    const float* Xp = X + (size_t)(m0 + xm) * ldx + xk;

    // W loader: NC rows x 16 k = NC*4 float4 over <=2 slots per thread
    int wc_[2], wk_[2];
    bool wval[2];
    const float* Wp[2];
#pragma unroll
    for (int i = 0; i < 2; i++) {
        int lin = t + 256 * i;
        wval[i] = (lin < NC * 4);
        int c = lin >> 2;
        if (c >= NC) c = 0;
        int ks = (lin & 3) * 4;
        int gs = c >> 5;
        int ga = ACT ? ((gs == 0) ? 0 : gs + 1) : gs;  // {i,g,o} or {i,f,g,o}
        wc_[i] = c; wk_[i] = ks;
        Wp[i] = W + (size_t)(ga * U + u0 + (c & 31)) * KTOT + ks;
    }

    float acc[4][2][NG];
#pragma unroll
    for (int a = 0; a < 4; a++)
#pragma unroll
        for (int b = 0; b < 2; b++)
#pragma unroll
            for (int g = 0; g < NG; g++) acc[a][b][g] = 0.0f;

    // prologue: tile 0 -> buffer 0
    float4 xr = *(const float4*)(Xp);
    float4 wr[2];
#pragma unroll
    for (int i = 0; i < 2; i++) if (wval[i]) wr[i] = *(const float4*)(Wp[i]);

    sXT[0][xk + 0][xm] = xr.x; sXT[0][xk + 1][xm] = xr.y;
    sXT[0][xk + 2][xm] = xr.z; sXT[0][xk + 3][xm] = xr.w;
#pragma unroll
    for (int i = 0; i < 2; i++) if (wval[i]) {
        sWT[0][wk_[i] + 0][wc_[i]] = wr[i].x;
        sWT[0][wk_[i] + 1][wc_[i]] = wr[i].y;
        sWT[0][wk_[i] + 2][wc_[i]] = wr[i].z;
        sWT[0][wk_[i] + 3][wc_[i]] = wr[i].w;
    }
    __syncthreads();

    const int nt = KTOT >> 4;
    for (int it = 0; it < nt; it++) {
        const int cb = it & 1;
        if (it + 1 < nt) {
            xr = *(const float4*)(Xp + (it + 1) * 16);
#pragma unroll
            for (int i = 0; i < 2; i++)
                if (wval[i]) wr[i] = *(const float4*)(Wp[i] + (it + 1) * 16);
        }
#pragma unroll
        for (int k = 0; k < 16; k++) {
            float4 xv = *(const float4*)&sXT[cb][k][ty * 4];
            float xa[4] = {xv.x, xv.y, xv.z, xv.w};
#pragma unroll
            for (int gs = 0; gs < NG; gs++) {
                float2 wv = *(const float2*)&sWT[cb][k][gs * 32 + tx * 2];
#pragma unroll
                for (int mm = 0; mm < 4; mm++) {
                    acc[mm][0][gs] += xa[mm] * wv.x;
                    acc[mm][1][gs] += xa[mm] * wv.y;
                }
            }
        }
        if (it + 1 < nt) {
            const int nb = (it + 1) & 1;
            sXT[nb][xk + 0][xm] = xr.x; sXT[nb][xk + 1][xm] = xr.y;
            sXT[nb][xk + 2][xm] = xr.z; sXT[nb][xk + 3][xm] = xr.w;
#pragma unroll
            for (int i = 0; i < 2; i++) if (wval[i]) {
                sWT[nb][wk_[i] + 0][wc_[i]] = wr[i].x;
                sWT[nb][wk_[i] + 1][wc_[i]] = wr[i].y;
                sWT[nb][wk_[i] + 2][wc_[i]] = wr[i].z;
                sWT[nb][wk_[i] + 3][wc_[i]] = wr[i].w;
            }
        }
        __syncthreads();
    }

    // epilogue
#pragma unroll
    for (int uu = 0; uu < 2; uu++) {
        const int ug = u0 + tx * 2 + uu;
        if constexpr (ACT) {
            float bi = bias[ug];
            float bg = bias[2 * U + ug];
            float bo = bias[3 * U + ug];
#pragma unroll
            for (int mm = 0; mm < 4; mm++) {
                float cc = sigf(acc[mm][uu][0] + bi) * tanhf(acc[mm][uu][1] + bg);
                float hh = sigf(acc[mm][uu][2] + bo) * tanhf(cc);
                out[(size_t)(m0 + ty * 4 + mm) * U + ug] = hh;
            }
        } else {
#pragma unroll
            for (int gs = 0; gs < NG; gs++)
#pragma unroll
                for (int mm = 0; mm < 4; mm++)
                    out[(size_t)(m0 + ty * 4 + mm) * (4 * U) + gs * U + ug] =
                        acc[mm][uu][gs];
        }
    }
}

// ------------------------------ note-axis scan -----------------------------
// 128 blocks x 8 batches, 256 threads. Thread owns unit u = t&127 for batches
// (t>>7)*4 .. +3. Weights staged per 16-k tile into double-buffered shared
// (pad-20 stride => conflict-free LDS.128).

__device__ __forceinline__ void load_wtile_regs(float4 pre[8],
                                                const float* __restrict__ W,
                                                int kt, int t) {
#pragma unroll
    for (int i = 0; i < 8; i++) {
        int lin = t + 256 * i;          // 0..2047 (512 rows x 4 float4)
        int r = lin >> 2, k4 = lin & 3;
        pre[i] = *(const float4*)&W[r * 128 + kt + k4 * 4];
    }
}

__device__ __forceinline__ void sts_wtile(float* dst, const float4 pre[8], int t) {
#pragma unroll
    for (int i = 0; i < 8; i++) {
        int lin = t + 256 * i;
        int r = lin >> 2, k4 = lin & 3;
        *(float4*)&dst[r * 20 + k4 * 4] = pre[i];
    }
}

__device__ __forceinline__ void accum_tile(float acc[4][4], const float* sWt,
                                           const float* sH, int kt, int u, int bp) {
#pragma unroll
    for (int kk = 0; kk < 16; kk += 4) {
        float4 wv[4];
#pragma unroll
        for (int g = 0; g < 4; g++)
            wv[g] = *(const float4*)&sWt[(g * 128 + u) * 20 + kk];
#pragma unroll
        for (int b = 0; b < 4; b++) {
            float4 hv = *(const float4*)&sH[(bp * 4 + b) * 128 + kt + kk];
#pragma unroll
            for (int g = 0; g < 4; g++) {
                acc[b][g] += hv.x * wv[g].x;
                acc[b][g] += hv.y * wv[g].y;
                acc[b][g] += hv.z * wv[g].z;
                acc[b][g] += hv.w * wv[g].w;
            }
        }
    }
}

__device__ __forceinline__ void gemm_pass(float acc[4][4],
                                          const float* __restrict__ W,
                                          const float* sH, float* sW,
                                          int t, int u, int bp) {
    float4 pre[8];
    load_wtile_regs(pre, W, 0, t);
    sts_wtile(sW, pre, t);
    __syncthreads();
    for (int it = 0; it < 8; it++) {
        float* cur = sW + (it & 1) * 10240;
        if (it < 7) load_wtile_regs(pre, W, (it + 1) * 16, t);
        accum_tile(acc, cur, sH, it * 16, u, bp);
        if (it < 7) sts_wtile(sW + ((it + 1) & 1) * 10240, pre, t);
        __syncthreads();
    }
}

__global__ __launch_bounds__(256, 1)
void scan_kernel(const float* __restrict__ targets,
                 const float* __restrict__ Whh0,
                 const float* __restrict__ nb0,
                 const float* __restrict__ Wih1,
                 const float* __restrict__ Whh1,
                 const float* __restrict__ nb1,
                 const float* __restrict__ outW,
                 const float* __restrict__ outb,
                 float* __restrict__ out) {
    extern __shared__ float sh[];
    float* sW  = sh;              // 2 x 512 x 20 = 20480
    float* sH1 = sh + 20480;      // 8 x 128
    float* sH2 = sH1 + 1024;      // 8 x 128
    float* sWo = sH2 + 1024;      // 128

    const int t = threadIdx.x;
    const int u = t & 127, bp = t >> 7;
    const int B0 = blockIdx.x * 8;

    if (t < 128) sWo[t] = outW[t];
    for (int i = t; i < 2048; i += 256) sH1[i] = 0.0f;  // zeros sH1+sH2

    float c1[4] = {0, 0, 0, 0}, c2[4] = {0, 0, 0, 0};
    float b0r[4], b1r[4], wcr[4];
#pragma unroll
    for (int g = 0; g < 4; g++) {
        b0r[g] = nb0[g * 128 + u];
        b1r[g] = nb1[g * 128 + u];
        wcr[g] = g_wc[g * 128 + u];
    }
    const float ob = outb[0];
    __syncthreads();

    for (int n = 0; n < NN; n++) {
        // ---- layer 0 ----
        float acc[4][4];
#pragma unroll
        for (int b = 0; b < 4; b++) {
            int bg = B0 + bp * 4 + b;
            float cond = (n == 0) ? 0.0f : targets[bg * NN + n - 1];
            size_t m = (size_t)bg * NN + n;
#pragma unroll
            for (int g = 0; g < 4; g++)
                acc[b][g] = g_xw[m * 512 + g * 128 + u] + b0r[g] + cond * wcr[g];
        }
        gemm_pass(acc, Whh0, sH1, sW, t, u, bp);

        float h1n[4];
#pragma unroll
        for (int b = 0; b < 4; b++) {
            float cc = sigf(acc[b][1]) * c1[b] + sigf(acc[b][0]) * tanhf(acc[b][2]);
            c1[b] = cc;
            h1n[b] = sigf(acc[b][3]) * tanhf(cc);
        }
        // gemm_pass ended with __syncthreads => all sH1 reads complete
#pragma unroll
        for (int b = 0; b < 4; b++) sH1[(bp * 4 + b) * 128 + u] = h1n[b];
        __syncthreads();

        // ---- layer 1 ----
        float acc2[4][4];
#pragma unroll
        for (int b = 0; b < 4; b++)
#pragma unroll
            for (int g = 0; g < 4; g++) acc2[b][g] = b1r[g];
        gemm_pass(acc2, Wih1, sH1, sW, t, u, bp);
        gemm_pass(acc2, Whh1, sH2, sW, t, u, bp);

        float h2n[4];
#pragma unroll
        for (int b = 0; b < 4; b++) {
            float cc = sigf(acc2[b][1]) * c2[b] + sigf(acc2[b][0]) * tanhf(acc2[b][2]);
            c2[b] = cc;
            h2n[b] = sigf(acc2[b][3]) * tanhf(cc);
        }
#pragma unroll
        for (int b = 0; b < 4; b++) sH2[(bp * 4 + b) * 128 + u] = h2n[b];
        __syncthreads();

        // ---- output: warp w handles batch w ----
        int w = t >> 5, lane = t & 31;
        float p = 0.0f;
#pragma unroll
        for (int j = 0; j < 4; j++)
            p += sH2[w * 128 + lane + 32 * j] * sWo[lane + 32 * j];
#pragma unroll
        for (int off = 16; off; off >>= 1)
            p += __shfl_down_sync(0xffffffffu, p, off);
        if (lane == 0) out[(B0 + w) * NN + n] = sigf(p + ob);
        // sH2 next written only after layer-1 passes (with internal barriers)
    }
}

// --------------------------------- launch ---------------------------------

extern "C" void kernel_launch(void* const* d_in, const int* in_sizes, int n_in,
                              void* d_out, int out_size) {
    (void)in_sizes; (void)n_in; (void)out_size;
    const float* note    = (const float*)d_in[0];
    const float* targets = (const float*)d_in[1];
    const float* tWih0   = (const float*)d_in[2];
    const float* tb0     = (const float*)d_in[4];
    const float* tWih1   = (const float*)d_in[5];
    const float* tb1     = (const float*)d_in[7];
    const float* nWih0   = (const float*)d_in[8];
    const float* nWhh0   = (const float*)d_in[9];
    const float* nb0     = (const float*)d_in[10];
    const float* nWih1   = (const float*)d_in[11];
    const float* nWhh1   = (const float*)d_in[12];
    const float* nb1     = (const float*)d_in[13];
    const float* outW    = (const float*)d_in[14];
    const float* outb    = (const float*)d_in[15];
    float* out = (float*)d_out;

    float *p_rnnin, *p_w0p, *p_h1, *p_feats, *p_w2p, *p_xw;
    cudaGetSymbolAddress((void**)&p_rnnin, g_rnnin);
    cudaGetSymbolAddress((void**)&p_w0p,   g_w0p);
    cudaGetSymbolAddress((void**)&p_h1,    g_h1);
    cudaGetSymbolAddress((void**)&p_feats, g_feats);
    cudaGetSymbolAddress((void**)&p_w2p,   g_w2p);
    cudaGetSymbolAddress((void**)&p_xw,    g_xw);

    build_rnnin<<<(MM * K1) / 256, 256>>>(note);
    pad_w0<<<(1024 * K1) / 256, 256>>>(tWih0);
    prep_w2<<<(512 * 256) / 256, 256>>>(nWih0);

    // h1 = act(rnn_in @ t_Wih0.T + b0)        (K padded to 64)
    lstm_gemm<256, true><<<dim3(768, 8), 256>>>(p_rnnin, K1, K1, p_w0p, tb0, p_h1);
    // feats = act(h1 @ t_Wih1.T + b1)
    lstm_gemm<256, true><<<dim3(768, 8), 256>>>(p_h1, 256, 256, tWih1, tb1, p_feats);
    // xw = feats @ n_Wih0[:, :256].T          (raw gates, bias added in scan)
    lstm_gemm<128, false><<<dim3(768, 4), 256>>>(p_feats, 256, 256, p_w2p, nullptr, p_xw);

    const int smem = 22656 * (int)sizeof(float);  // 90624 B
    cudaFuncSetAttribute(scan_kernel, cudaFuncAttributeMaxDynamicSharedMemorySize, smem);
    scan_kernel<<<128, 256, smem>>>(targets, nWhh0, nb0, nWih1, nWhh1, nb1,
                                    outW, outb, out);
}